// round 11
// baseline (speedup 1.0000x reference)
#include <cuda_runtime.h>
#include <cuda_bf16.h>
#include <cstdint>

#define BATCH 8
#define NB    16     // both images / both paths merged
#define C_IN  256
#define C_MID 1024
#define HW    4096   // 64*64
#define PHW   1024   // 32*32
typedef __nv_bfloat16 bf16;

// ---------------- scratch (static device globals; no allocation) ----------------
__device__ bf16 g_XTh[(size_t)NB * HW * C_IN];   // quad pixel order
__device__ bf16 g_XTl[(size_t)NB * HW * C_IN];
__device__ bf16 g_Wh [(size_t)C_MID * C_IN];
__device__ bf16 g_Wl [(size_t)C_MID * C_IN];
__device__ bf16 g_Fh [(size_t)NB * C_MID * PHW];   // [0..7]=Fa, [8..15]=Fb
__device__ bf16 g_Fl [(size_t)NB * C_MID * PHW];
__device__ bf16 g_FTh[(size_t)NB * PHW * C_MID];
__device__ bf16 g_FTl[(size_t)NB * PHW * C_MID];
__device__ bf16 g_WTh[(size_t)2 * C_MID * C_MID];  // [0]=WeT, [1]=We2T
__device__ bf16 g_WTl[(size_t)2 * C_MID * C_MID];
__device__ bf16 g_GTh[(size_t)NB * PHW * C_MID];
__device__ bf16 g_GTl[(size_t)NB * PHW * C_MID];
__device__ float g_MT[(size_t)NB * PHW * PHW];
__device__ bf16 g_MTh[(size_t)NB * PHW * PHW];
__device__ bf16 g_MTl[(size_t)NB * PHW * PHW];
__device__ bf16 g_ETh[(size_t)NB * C_MID * PHW];
__device__ bf16 g_ETl[(size_t)NB * C_MID * PHW];
__device__ bf16 g_C2h[(size_t)256 * C_MID];
__device__ bf16 g_C2l[(size_t)256 * C_MID];
__device__ float g_V [(size_t)NB * 256 * PHW];

// ================= helpers =================
__device__ __forceinline__ uint32_t smem_u32(const void* p) {
    uint32_t a;
    asm("{ .reg .u64 t; cvta.to.shared.u64 t, %1; cvt.u32.u64 %0, t; }" : "=r"(a) : "l"(p));
    return a;
}
__device__ __forceinline__ void ldsm4(uint32_t* r, uint32_t addr) {
    asm volatile("ldmatrix.sync.aligned.m8n8.x4.shared.b16 {%0,%1,%2,%3}, [%4];"
                 : "=r"(r[0]), "=r"(r[1]), "=r"(r[2]), "=r"(r[3]) : "r"(addr));
}
__device__ __forceinline__ void mma16816(float* d, const uint32_t* a, const uint32_t* b) {
    asm volatile(
        "mma.sync.aligned.m16n8k16.row.col.f32.bf16.bf16.f32 "
        "{%0,%1,%2,%3}, {%4,%5,%6,%7}, {%8,%9}, {%0,%1,%2,%3};"
        : "+f"(d[0]), "+f"(d[1]), "+f"(d[2]), "+f"(d[3])
        : "r"(a[0]), "r"(a[1]), "r"(a[2]), "r"(a[3]), "r"(b[0]), "r"(b[1]));
}
__device__ __forceinline__ uint32_t packbf(float x, float y) {
    uint32_t r;
    asm("cvt.rn.bf16x2.f32 %0, %1, %2;" : "=r"(r) : "f"(y), "f"(x));
    return r;
}
__device__ __forceinline__ float bflo(uint32_t p) { return __uint_as_float(p << 16); }
__device__ __forceinline__ float bfhi(uint32_t p) { return __uint_as_float(p & 0xFFFF0000u); }

// ================= tensor GEMM: 128x64 tile, 128 thr, 2 CTAs/SM, ks-pipelined ===
// C[i,j](+bias[i]) = sum_k (Ah+Al)[i,k] * (Bh+Bl)[j,k]  (3-term split)
// A batch: bz.  B batch: (bz ^ bXor) >> bShr.
// mode 0: fp32 C.  mode 1: split bf16 Ch/Cl.
// mode 2: conv1 pooled epilogue — B pixels in QUAD order; tile 64 pix = 16 quads.
#define KC        32
#define ROWS_B16  40
#define OFF_AL    10240     // Ah: 128*40*2
#define OFF_BH    20480
#define OFF_BL    25600     // Bh: 64*40*2 = 5120
#define STG_B     30720
#define SM_TOTAL  61440

#define LOAD_FRAGS(P, SB, KO)                                                        \
    do {                                                                             \
        _Pragma("unroll")                                                            \
        for (int mt = 0; mt < 4; mt++)                                               \
            ldsm4(f_ah[P][mt], (SB) + (uint32_t)(a_base + mt * 16 * ROWS_B16 + (KO)) * 2); \
        _Pragma("unroll")                                                            \
        for (int mt = 0; mt < 4; mt++)                                               \
            ldsm4(f_al[P][mt], (SB) + OFF_AL + (uint32_t)(a_base + mt * 16 * ROWS_B16 + (KO)) * 2); \
        _Pragma("unroll")                                                            \
        for (int nt2 = 0; nt2 < 2; nt2++) {                                          \
            uint32_t t[4];                                                           \
            ldsm4(t, (SB) + OFF_BH + (uint32_t)(b_base + nt2 * 16 * ROWS_B16 + (KO)) * 2); \
            f_bh[P][nt2*2][0] = t[0]; f_bh[P][nt2*2][1] = t[1];                      \
            f_bh[P][nt2*2+1][0] = t[2]; f_bh[P][nt2*2+1][1] = t[3];                  \
        }                                                                            \
        _Pragma("unroll")                                                            \
        for (int nt2 = 0; nt2 < 2; nt2++) {                                          \
            uint32_t t[4];                                                           \
            ldsm4(t, (SB) + OFF_BL + (uint32_t)(b_base + nt2 * 16 * ROWS_B16 + (KO)) * 2); \
            f_bl[P][nt2*2][0] = t[0]; f_bl[P][nt2*2][1] = t[1];                      \
            f_bl[P][nt2*2+1][0] = t[2]; f_bl[P][nt2*2+1][1] = t[3];                  \
        }                                                                            \
    } while (0)

#define DO_MMA(P)                                                                    \
    do {                                                                             \
        _Pragma("unroll")                                                            \
        for (int mt = 0; mt < 4; mt++)                                               \
            _Pragma("unroll")                                                        \
            for (int nt = 0; nt < 4; nt++)                                           \
                mma16816(acc[mt][nt], f_ah[P][mt], f_bh[P][nt]);                     \
        _Pragma("unroll")                                                            \
        for (int mt = 0; mt < 4; mt++)                                               \
            _Pragma("unroll")                                                        \
            for (int nt = 0; nt < 4; nt++)                                           \
                mma16816(acc[mt][nt], f_ah[P][mt], f_bl[P][nt]);                     \
        _Pragma("unroll")                                                            \
        for (int mt = 0; mt < 4; mt++)                                               \
            _Pragma("unroll")                                                        \
            for (int nt = 0; nt < 4; nt++)                                           \
                mma16816(acc[mt][nt], f_al[P][mt], f_bh[P][nt]);                     \
    } while (0)

#define STAGE_STORE(BASE)                                                            \
    do {                                                                             \
        char* base_ = (BASE);                                                        \
        *reinterpret_cast<uint4*>(base_ + stsA)                 = rgAh[0];           \
        *reinterpret_cast<uint4*>(base_ + stsA + 16)            = rgAh[1];           \
        *reinterpret_cast<uint4*>(base_ + stsA + 32)            = rgAh[2];           \
        *reinterpret_cast<uint4*>(base_ + stsA + 48)            = rgAh[3];           \
        *reinterpret_cast<uint4*>(base_ + OFF_AL + stsA)        = rgAl[0];           \
        *reinterpret_cast<uint4*>(base_ + OFF_AL + stsA + 16)   = rgAl[1];           \
        *reinterpret_cast<uint4*>(base_ + OFF_AL + stsA + 32)   = rgAl[2];           \
        *reinterpret_cast<uint4*>(base_ + OFF_AL + stsA + 48)   = rgAl[3];           \
        *reinterpret_cast<uint4*>(base_ + OFF_BH + stsB)        = rgBh[0];           \
        *reinterpret_cast<uint4*>(base_ + OFF_BH + stsB + 16)   = rgBh[1];           \
        *reinterpret_cast<uint4*>(base_ + OFF_BL + stsB)        = rgBl[0];           \
        *reinterpret_cast<uint4*>(base_ + OFF_BL + stsB + 16)   = rgBl[1];           \
    } while (0)

#define STAGE_LOAD()                                                                 \
    do {                                                                             \
        rgAh[0] = *reinterpret_cast<const uint4*>(pAh);                              \
        rgAh[1] = *reinterpret_cast<const uint4*>(pAh + 8);                          \
        rgAh[2] = *reinterpret_cast<const uint4*>(pAh + 16);                         \
        rgAh[3] = *reinterpret_cast<const uint4*>(pAh + 24);                         \
        rgAl[0] = *reinterpret_cast<const uint4*>(pAl);                              \
        rgAl[1] = *reinterpret_cast<const uint4*>(pAl + 8);                          \
        rgAl[2] = *reinterpret_cast<const uint4*>(pAl + 16);                         \
        rgAl[3] = *reinterpret_cast<const uint4*>(pAl + 24);                         \
        rgBh[0] = *reinterpret_cast<const uint4*>(pBh);                              \
        rgBh[1] = *reinterpret_cast<const uint4*>(pBh + 8);                          \
        rgBl[0] = *reinterpret_cast<const uint4*>(pBl);                              \
        rgBl[1] = *reinterpret_cast<const uint4*>(pBl + 8);                          \
    } while (0)

__global__ __launch_bounds__(128) void tgemm(
    const bf16* __restrict__ Ah, const bf16* __restrict__ Al, long lda, long saB,
    const bf16* __restrict__ Bh, const bf16* __restrict__ Bl, long ldb, long sbB,
    float* __restrict__ C, bf16* __restrict__ Ch, bf16* __restrict__ Cl,
    long ldc, long scB, int K, const float* __restrict__ bias,
    int mode, int bXor, int bShr)
{
    extern __shared__ char smem[];
    const uint32_t s0 = smem_u32(smem);
    const int tid = threadIdx.x;
    const int lane = tid & 31;
    const int wid = tid >> 5;         // 0..3
    const int bz = blockIdx.z;
    Ah += (long)bz * saB; Al += (long)bz * saB;
    const long bOff = (long)((bz ^ bXor) >> bShr) * sbB;
    Bh += bOff; Bl += bOff;
    const long i0 = (long)blockIdx.y * 128;
    const long j0 = (long)blockIdx.x * 64;

    // staging: A row = tid (0..127), 32 k per row; B row = tid>>1 (0..63), k-half
    const bf16* pAh = Ah + (i0 + tid) * lda;
    const bf16* pAl = Al + (i0 + tid) * lda;
    const bf16* pBh = Bh + (j0 + (tid >> 1)) * ldb + ((tid & 1) << 4);
    const bf16* pBl = Bl + (j0 + (tid >> 1)) * ldb + ((tid & 1) << 4);
    const int stsA = tid * 80;                               // 40 bf16 * 2B
    const int stsB = (tid >> 1) * 80 + ((tid & 1) << 5);

    // warp tile: m0 in {0,64}, n0 in {0,32}
    const int m0 = (wid & 1) * 64;
    const int n0 = (wid >> 1) * 32;
    const int a_base = (m0 + (lane & 15)) * ROWS_B16 + ((lane >> 4) << 3);
    const int b_base = (n0 + ((lane >> 4) << 3) + (lane & 7)) * ROWS_B16 +
                       (((lane >> 3) & 1) << 3);

    float acc[4][4][4];
#pragma unroll
    for (int mt = 0; mt < 4; mt++)
#pragma unroll
        for (int nt = 0; nt < 4; nt++)
#pragma unroll
            for (int e = 0; e < 4; e++) acc[mt][nt][e] = 0.f;

    uint32_t f_ah[2][4][4], f_al[2][4][4], f_bh[2][4][2], f_bl[2][4][2];
    uint4 rgAh[4], rgAl[4], rgBh[2], rgBl[2];

    const int NC = K >> 5;

    // prologue: stage chunk 0 into buf0, prefetch chunk 1 regs
    STAGE_LOAD();
    STAGE_STORE(smem);
    if (NC > 1) {
        pAh += KC; pAl += KC; pBh += KC; pBl += KC;
        STAGE_LOAD();
    }
    __syncthreads();
    LOAD_FRAGS(0, s0, 0);

    for (int c = 0; c < NC; c++) {
        const uint32_t sb = s0 + (uint32_t)(c & 1) * STG_B;
        LOAD_FRAGS(1, sb, 16);
        DO_MMA(0);
        if (c + 1 < NC) {
            STAGE_STORE(smem + ((c + 1) & 1) * STG_B);
            if (c + 2 < NC) {
                pAh += KC; pAl += KC; pBh += KC; pBl += KC;
                STAGE_LOAD();
            }
        }
        DO_MMA(1);
        __syncthreads();
        if (c + 1 < NC)
            LOAD_FRAGS(0, s0 + (uint32_t)((c + 1) & 1) * STG_B, 0);
    }

    const int er = lane >> 2;
    const int ec = (lane & 3) << 1;

    if (mode == 2) {
        // conv1 pooled epilogue: tile = 128 ch x 64 pix (16 quads, quad order).
        float* spool = reinterpret_cast<float*>(smem);   // 128 x 68
#pragma unroll
        for (int mt = 0; mt < 4; mt++) {
            int r0 = m0 + mt * 16 + er;
#pragma unroll
            for (int nt = 0; nt < 4; nt++) {
                int jc = n0 + nt * 8 + ec;
                *reinterpret_cast<float2*>(&spool[(r0)     * 68 + jc]) =
                    make_float2(acc[mt][nt][0], acc[mt][nt][1]);
                *reinterpret_cast<float2*>(&spool[(r0 + 8) * 68 + jc]) =
                    make_float2(acc[mt][nt][2], acc[mt][nt][3]);
            }
        }
        __syncthreads();
        const int cl = tid;               // channel 0..127
        const float bv = bias[i0 + cl];
        uint32_t hw[8], lw[8];
#pragma unroll
        for (int o = 0; o < 16; o += 2) {
            float vv[2];
#pragma unroll
            for (int u = 0; u < 2; u++) {
                const float4 q = *reinterpret_cast<const float4*>(&spool[cl * 68 + 4 * (o + u)]);
                vv[u] = fmaxf(fmaxf(q.x, q.y), fmaxf(q.z, q.w)) + bv;
            }
            uint32_t hp = packbf(vv[0], vv[1]);
            hw[o >> 1] = hp;
            lw[o >> 1] = packbf(vv[0] - bflo(hp), vv[1] - bfhi(hp));
        }
        long off = (long)bz * scB + (i0 + cl) * ldc + (j0 >> 2);
        *reinterpret_cast<uint4*>(Ch + off)     = *reinterpret_cast<uint4*>(hw);
        *reinterpret_cast<uint4*>(Ch + off + 8) = *reinterpret_cast<uint4*>(hw + 4);
        *reinterpret_cast<uint4*>(Cl + off)     = *reinterpret_cast<uint4*>(lw);
        *reinterpret_cast<uint4*>(Cl + off + 8) = *reinterpret_cast<uint4*>(lw + 4);
        return;
    }

#pragma unroll
    for (int mt = 0; mt < 4; mt++) {
        long r0 = i0 + m0 + mt * 16 + er;
        long r1 = r0 + 8;
        float bv0 = bias ? bias[r0] : 0.f;
        float bv1 = bias ? bias[r1] : 0.f;
#pragma unroll
        for (int nt = 0; nt < 4; nt++) {
            long jc = j0 + n0 + nt * 8 + ec;
            float o00 = acc[mt][nt][0] + bv0, o01 = acc[mt][nt][1] + bv0;
            float o10 = acc[mt][nt][2] + bv1, o11 = acc[mt][nt][3] + bv1;
            if (mode == 0) {
                float* cb = C + (long)bz * scB;
                *reinterpret_cast<float2*>(cb + r0 * ldc + jc) = make_float2(o00, o01);
                *reinterpret_cast<float2*>(cb + r1 * ldc + jc) = make_float2(o10, o11);
            } else {
                bf16* chb = Ch + (long)bz * scB;
                bf16* clb = Cl + (long)bz * scB;
                uint32_t h0 = packbf(o00, o01);
                uint32_t h1 = packbf(o10, o11);
                *reinterpret_cast<uint32_t*>(chb + r0 * ldc + jc) = h0;
                *reinterpret_cast<uint32_t*>(chb + r1 * ldc + jc) = h1;
                *reinterpret_cast<uint32_t*>(clb + r0 * ldc + jc) =
                    packbf(o00 - bflo(h0), o01 - bfhi(h0));
                *reinterpret_cast<uint32_t*>(clb + r1 * ldc + jc) =
                    packbf(o10 - bflo(h1), o11 - bfhi(h1));
            }
        }
    }
}

// ================= conversion / movement kernels =================
// fp32 [bz][R][Cc] -> split bf16 [bz][Cc][R]  (plain transpose)
__global__ void trans_split_kernel(const float* __restrict__ in,
                                   bf16* __restrict__ oh, bf16* __restrict__ ol,
                                   int R, int Cc)
{
    __shared__ float t[32][33];
    int bx = blockIdx.x * 32, by = blockIdx.y * 32;
    long base = (long)blockIdx.z * (long)R * Cc;
    int x = threadIdx.x, y = threadIdx.y;  // 32 x 8
#pragma unroll
    for (int i = 0; i < 32; i += 8)
        t[y + i][x] = in[base + (long)(by + y + i) * Cc + bx + x];
    __syncthreads();
#pragma unroll
    for (int i = 0; i < 32; i += 8) {
        float v = t[x][y + i];
        bf16 h = __float2bfloat16(v);
        long o = base + (long)(bx + y + i) * R + by + x;
        oh[o] = h;
        ol[o] = __float2bfloat16(v - __bfloat162float(h));
    }
}

// x [bz][C][64][64] -> XT [bz][p'][C] with p' in 2x2-quad order
__global__ void trans_split_quad_kernel(const float* __restrict__ in,
                                        bf16* __restrict__ oh, bf16* __restrict__ ol,
                                        int R, int Cc)
{
    __shared__ float t[32][33];
    int bx = blockIdx.x * 32, by = blockIdx.y * 32;
    long base = (long)blockIdx.z * (long)R * Cc;
    int x = threadIdx.x, y = threadIdx.y;  // 32 x 8
#pragma unroll
    for (int i = 0; i < 32; i += 8)
        t[y + i][x] = in[base + (long)(by + y + i) * Cc + bx + x];
    __syncthreads();
#pragma unroll
    for (int i = 0; i < 32; i += 8) {
        float v = t[x][y + i];
        bf16 h = __float2bfloat16(v);
        int p = bx + y + i;                 // linear pixel h*64+w
        int hh = p >> 6, ww = p & 63;
        int pq = (((hh >> 1) << 5) + (ww >> 1)) * 4 + ((hh & 1) << 1) + (ww & 1);
        long o = base + (long)pq * R + by + x;
        oh[o] = h;
        ol[o] = __float2bfloat16(v - __bfloat162float(h));
    }
}

__global__ void split_kernel(const float* __restrict__ in,
                             bf16* __restrict__ oh, bf16* __restrict__ ol, int n)
{
    int i = blockIdx.x * 256 + threadIdx.x;
    if (i >= n) return;
    float v = in[i];
    bf16 h = __float2bfloat16(v);
    oh[i] = h;
    ol[i] = __float2bfloat16(v - __bfloat162float(h));
}

__global__ void trans_b16_kernel(const bf16* __restrict__ ih, const bf16* __restrict__ il,
                                 bf16* __restrict__ oh, bf16* __restrict__ ol,
                                 int R, int Cc)
{
    __shared__ bf16 th[32][34];
    __shared__ bf16 tl[32][34];
    int bx = blockIdx.x * 32, by = blockIdx.y * 32;
    long base = (long)blockIdx.z * (long)R * Cc;
    int x = threadIdx.x, y = threadIdx.y;
#pragma unroll
    for (int i = 0; i < 32; i += 8) {
        long o = base + (long)(by + y + i) * Cc + bx + x;
        th[y + i][x] = ih[o];
        tl[y + i][x] = il[o];
    }
    __syncthreads();
#pragma unroll
    for (int i = 0; i < 32; i += 8) {
        long o = base + (long)(bx + y + i) * R + by + x;
        oh[o] = th[x][y + i];
        ol[o] = tl[x][y + i];
    }
}

__global__ void normsplit_kernel(const float* __restrict__ T,
                                 bf16* __restrict__ oh, bf16* __restrict__ ol)
{
    __shared__ float part[4][64];
    __shared__ float sinv[64];
    int pp = threadIdx.x & 63, qs = threadIdx.x >> 6;
    int p = blockIdx.x * 64 + pp;
    long base = (long)blockIdx.y * PHW * PHW;
    float ss = 0.f;
#pragma unroll 4
    for (int q = qs * 256; q < qs * 256 + 256; q++) {
        float x = fmaxf(T[base + (long)q * PHW + p], 0.f);
        ss += x * x;
    }
    part[qs][pp] = ss;
    __syncthreads();
    if (threadIdx.x < 64) {
        float s = part[0][threadIdx.x] + part[1][threadIdx.x] +
                  part[2][threadIdx.x] + part[3][threadIdx.x];
        sinv[threadIdx.x] = rsqrtf(s + 1e-6f);
    }
    __syncthreads();
    float inv = sinv[pp];
#pragma unroll 4
    for (int q = qs * 256; q < qs * 256 + 256; q++) {
        long idx = base + (long)q * PHW + p;
        float v = fmaxf(T[idx], 0.f) * inv;
        bf16 h = __float2bfloat16(v);
        oh[idx] = h;
        ol[idx] = __float2bfloat16(v - __bfloat162float(h));
    }
}

__global__ void upsample_kernel(const float* __restrict__ V, float* __restrict__ O)
{
    long i = (long)blockIdx.x * blockDim.x + threadIdx.x;
    int x = (int)(i & 63);
    int y = (int)((i >> 6) & 63);
    long co = i >> 12;
    const float s = 31.0f / 63.0f;
    float ys = y * s, xs = x * s;
    int y0 = (int)floorf(ys), x0 = (int)floorf(xs);
    float ty = ys - (float)y0, txx = xs - (float)x0;
    int y1 = min(y0 + 1, 31), x1 = min(x0 + 1, 31);
    const float* v = V + co * 1024;
    float v00 = v[y0 * 32 + x0], v01 = v[y0 * 32 + x1];
    float v10 = v[y1 * 32 + x0], v11 = v[y1 * 32 + x1];
    O[i] = (1.f - ty) * ((1.f - txx) * v00 + txx * v01) +
           ty * ((1.f - txx) * v10 + txx * v11);
}

// ================= launch =================
extern "C" void kernel_launch(void* const* d_in, const int* in_sizes, int n_in,
                              void* d_out, int out_size)
{
    const float* xa      = (const float*)d_in[0];
    const float* xb      = (const float*)d_in[1];
    const float* conv_w  = (const float*)d_in[2];
    const float* conv_b  = (const float*)d_in[3];
    const float* We      = (const float*)d_in[4];
    const float* We2     = (const float*)d_in[5];
    const float* conv2_w = (const float*)d_in[6];
    const float* conv2_b = (const float*)d_in[7];
    float* out = (float*)d_out;

    bf16 *XTh, *XTl, *Wh, *Wl, *Fh, *Fl, *FTh, *FTl, *WTh, *WTl;
    bf16 *GTh, *GTl, *MTh, *MTl, *ETh, *ETl, *C2h, *C2l;
    float *MT, *V;
    cudaGetSymbolAddress((void**)&XTh, g_XTh);  cudaGetSymbolAddress((void**)&XTl, g_XTl);
    cudaGetSymbolAddress((void**)&Wh,  g_Wh);   cudaGetSymbolAddress((void**)&Wl,  g_Wl);
    cudaGetSymbolAddress((void**)&Fh,  g_Fh);   cudaGetSymbolAddress((void**)&Fl,  g_Fl);
    cudaGetSymbolAddress((void**)&FTh, g_FTh);  cudaGetSymbolAddress((void**)&FTl, g_FTl);
    cudaGetSymbolAddress((void**)&WTh, g_WTh);  cudaGetSymbolAddress((void**)&WTl, g_WTl);
    cudaGetSymbolAddress((void**)&GTh, g_GTh);  cudaGetSymbolAddress((void**)&GTl, g_GTl);
    cudaGetSymbolAddress((void**)&MT,  g_MT);
    cudaGetSymbolAddress((void**)&MTh, g_MTh);  cudaGetSymbolAddress((void**)&MTl, g_MTl);
    cudaGetSymbolAddress((void**)&ETh, g_ETh);  cudaGetSymbolAddress((void**)&ETl, g_ETl);
    cudaGetSymbolAddress((void**)&C2h, g_C2h);  cudaGetSymbolAddress((void**)&C2l, g_C2l);
    cudaGetSymbolAddress((void**)&V,   g_V);

    cudaFuncSetAttribute(tgemm, cudaFuncAttributeMaxDynamicSharedMemorySize, SM_TOTAL);

    const long MM = (long)PHW * C_MID;   // 1M elems per batch
    dim3 tp(32, 8);

    // weights -> split bf16
    split_kernel<<<(C_MID * C_IN + 255) / 256, 256>>>(conv_w, Wh, Wl, C_MID * C_IN);
    split_kernel<<<(256 * C_MID + 255) / 256, 256>>>(conv2_w, C2h, C2l, 256 * C_MID);
    // We/We2 -> transposed split (WT[0], WT[1])
    trans_split_kernel<<<dim3(32, 32, 1), tp>>>(We,  WTh, WTl, C_MID, C_MID);
    trans_split_kernel<<<dim3(32, 32, 1), tp>>>(We2, WTh + (size_t)C_MID * C_MID,
                                                WTl + (size_t)C_MID * C_MID, C_MID, C_MID);
    // xa -> XT[0..7], xb -> XT[8..15]  (quad pixel order)
    trans_split_quad_kernel<<<dim3(128, 8, BATCH), tp>>>(xa, XTh, XTl, C_IN, HW);
    trans_split_quad_kernel<<<dim3(128, 8, BATCH), tp>>>(
        xb, XTh + (size_t)BATCH * HW * C_IN, XTl + (size_t)BATCH * HW * C_IN, C_IN, HW);

    // conv1 + fused 2x2 maxpool -> split F[c][q], all 16 batches
    tgemm<<<dim3(HW / 64, C_MID / 128, NB), 128, SM_TOTAL>>>(
        Wh, Wl, C_IN, 0,
        XTh, XTl, C_IN, (long)HW * C_IN,
        nullptr, Fh, Fl, PHW, MM, C_IN, conv_b, 2, 0, 0);

    // F -> FT (both split halves), all 16
    trans_b16_kernel<<<dim3(32, 32, NB), tp>>>(Fh, Fl, FTh, FTl, C_MID, PHW);

    // GT[q,c] = sum_d FT[q,d] * WT[path][c,d]   (path = bz>>3)
    tgemm<<<dim3(C_MID / 64, PHW / 128, NB), 128, SM_TOTAL>>>(
        FTh, FTl, C_MID, MM,
        WTh, WTl, C_MID, (long)C_MID * C_MID,
        nullptr, GTh, GTl, C_MID, MM, C_MID, nullptr, 1, 0, 3);

    // fmT[q,p] = sum_c GT[q,c] * FT_other[p,c]   (other image = bz^8)
    tgemm<<<dim3(PHW / 64, PHW / 128, NB), 128, SM_TOTAL>>>(
        GTh, GTl, C_MID, MM,
        FTh, FTl, C_MID, MM,
        MT, nullptr, nullptr, PHW, MM, C_MID, nullptr, 0, 8, 0);

    // relu + L2 norm over q per column p, write split
    normsplit_kernel<<<dim3(PHW / 64, NB), 256>>>(MT, MTh, MTl);

    // ET[k,q] = sum_p F[k,p] * Mn[q,p]
    tgemm<<<dim3(PHW / 64, C_MID / 128, NB), 128, SM_TOTAL>>>(
        Fh, Fl, PHW, MM,
        MTh, MTl, PHW, MM,
        nullptr, ETh, ETl, PHW, MM, PHW, nullptr, 1, 0, 0);

    // V[o,k] = sum_q c2w[o,q] * ET[k,q] + b
    tgemm<<<dim3(PHW / 64, 256 / 128, NB), 128, SM_TOTAL>>>(
        C2h, C2l, C_MID, 0,
        ETh, ETl, C_MID, MM,
        V, nullptr, nullptr, PHW, (long)256 * PHW, C_MID, conv2_b, 0, 0, 0);

    // upsample 2x align_corners, all 16 batches straight into out
    upsample_kernel<<<(NB * 256 * HW) / 256, 256>>>(V, out);
}

// round 16
// speedup vs baseline: 1.5498x; 1.5498x over previous
#include <cuda_runtime.h>
#include <cuda_bf16.h>
#include <cstdint>

#define BATCH 8
#define NB    16     // both images / both paths merged
#define C_IN  256
#define C_MID 1024
#define HW    4096   // 64*64
#define PHW   1024   // 32*32
typedef __nv_bfloat16 bf16;

// ---------------- scratch (static device globals; no allocation) ----------------
__device__ bf16 g_XTh[(size_t)NB * HW * C_IN];
__device__ bf16 g_XTl[(size_t)NB * HW * C_IN];
__device__ bf16 g_Wh [(size_t)C_MID * C_IN];
__device__ bf16 g_Wl [(size_t)C_MID * C_IN];
__device__ bf16 g_Fh [(size_t)NB * C_MID * PHW];   // [0..7]=Fa, [8..15]=Fb
__device__ bf16 g_Fl [(size_t)NB * C_MID * PHW];
__device__ bf16 g_FTh[(size_t)NB * PHW * C_MID];
__device__ bf16 g_FTl[(size_t)NB * PHW * C_MID];
__device__ bf16 g_WTh[(size_t)2 * C_MID * C_MID];  // [0]=WeT, [1]=We2T
__device__ bf16 g_WTl[(size_t)2 * C_MID * C_MID];
__device__ bf16 g_GTh[(size_t)NB * PHW * C_MID];
__device__ bf16 g_GTl[(size_t)NB * PHW * C_MID];
__device__ float g_MT[(size_t)NB * PHW * PHW];
__device__ bf16 g_MTh[(size_t)NB * PHW * PHW];
__device__ bf16 g_MTl[(size_t)NB * PHW * PHW];
__device__ bf16 g_ETh[(size_t)NB * C_MID * PHW];
__device__ bf16 g_ETl[(size_t)NB * C_MID * PHW];
__device__ bf16 g_C2h[(size_t)256 * C_MID];
__device__ bf16 g_C2l[(size_t)256 * C_MID];
__device__ float g_V [(size_t)NB * 256 * PHW];

// ================= helpers =================
__device__ __forceinline__ uint32_t smem_u32(const void* p) {
    uint32_t a;
    asm("{ .reg .u64 t; cvta.to.shared.u64 t, %1; cvt.u32.u64 %0, t; }" : "=r"(a) : "l"(p));
    return a;
}
__device__ __forceinline__ void ldsm4(uint32_t* r, uint32_t addr) {
    asm volatile("ldmatrix.sync.aligned.m8n8.x4.shared.b16 {%0,%1,%2,%3}, [%4];"
                 : "=r"(r[0]), "=r"(r[1]), "=r"(r[2]), "=r"(r[3]) : "r"(addr));
}
__device__ __forceinline__ void mma16816(float* d, const uint32_t* a, const uint32_t* b) {
    asm volatile(
        "mma.sync.aligned.m16n8k16.row.col.f32.bf16.bf16.f32 "
        "{%0,%1,%2,%3}, {%4,%5,%6,%7}, {%8,%9}, {%0,%1,%2,%3};"
        : "+f"(d[0]), "+f"(d[1]), "+f"(d[2]), "+f"(d[3])
        : "r"(a[0]), "r"(a[1]), "r"(a[2]), "r"(a[3]), "r"(b[0]), "r"(b[1]));
}
__device__ __forceinline__ uint32_t packbf(float x, float y) {
    uint32_t r;
    asm("cvt.rn.bf16x2.f32 %0, %1, %2;" : "=r"(r) : "f"(y), "f"(x));
    return r;
}
__device__ __forceinline__ float bflo(uint32_t p) { return __uint_as_float(p << 16); }
__device__ __forceinline__ float bfhi(uint32_t p) { return __uint_as_float(p & 0xFFFF0000u); }

// ================= tensor GEMM: 128x128 tile, templated K-chunk =================
// C[i,j](+bias[i]) = sum_k (Ah+Al)[i,k] * (Bh+Bl)[j,k]  (3-term split)
// A batch: bz.  B batch: (bz ^ bXor) >> bShr.
// mode 0: fp32 C.  mode 1: split bf16 Ch/Cl.
// mode 2 (KCH=32 only): conv1 pooled epilogue -> F[c][q] AND FT[q][c] (fused).

#define LOAD_FRAGS(P, SB, KO)                                                        \
    do {                                                                             \
        _Pragma("unroll")                                                            \
        for (int mt = 0; mt < 4; mt++)                                               \
            ldsm4(f_ah[P][mt], (SB) + (uint32_t)(a_base + mt * 16 * ROWSB + (KO)) * 2); \
        _Pragma("unroll")                                                            \
        for (int mt = 0; mt < 4; mt++)                                               \
            ldsm4(f_al[P][mt], (SB) + ARRB + (uint32_t)(a_base + mt * 16 * ROWSB + (KO)) * 2); \
        _Pragma("unroll")                                                            \
        for (int nt2 = 0; nt2 < 2; nt2++) {                                          \
            uint32_t t[4];                                                           \
            ldsm4(t, (SB) + 2*ARRB + (uint32_t)(b_base + nt2 * 16 * ROWSB + (KO)) * 2); \
            f_bh[P][nt2*2][0] = t[0]; f_bh[P][nt2*2][1] = t[1];                      \
            f_bh[P][nt2*2+1][0] = t[2]; f_bh[P][nt2*2+1][1] = t[3];                  \
        }                                                                            \
        _Pragma("unroll")                                                            \
        for (int nt2 = 0; nt2 < 2; nt2++) {                                          \
            uint32_t t[4];                                                           \
            ldsm4(t, (SB) + 3*ARRB + (uint32_t)(b_base + nt2 * 16 * ROWSB + (KO)) * 2); \
            f_bl[P][nt2*2][0] = t[0]; f_bl[P][nt2*2][1] = t[1];                      \
            f_bl[P][nt2*2+1][0] = t[2]; f_bl[P][nt2*2+1][1] = t[3];                  \
        }                                                                            \
    } while (0)

#define DO_MMA(P)                                                                    \
    do {                                                                             \
        _Pragma("unroll")                                                            \
        for (int mt = 0; mt < 4; mt++)                                               \
            _Pragma("unroll")                                                        \
            for (int nt = 0; nt < 4; nt++)                                           \
                mma16816(acc[mt][nt], f_ah[P][mt], f_bh[P][nt]);                     \
        _Pragma("unroll")                                                            \
        for (int mt = 0; mt < 4; mt++)                                               \
            _Pragma("unroll")                                                        \
            for (int nt = 0; nt < 4; nt++)                                           \
                mma16816(acc[mt][nt], f_ah[P][mt], f_bl[P][nt]);                     \
        _Pragma("unroll")                                                            \
        for (int mt = 0; mt < 4; mt++)                                               \
            _Pragma("unroll")                                                        \
            for (int nt = 0; nt < 4; nt++)                                           \
                mma16816(acc[mt][nt], f_al[P][mt], f_bh[P][nt]);                     \
    } while (0)

#define STAGE_LOAD()                                                                 \
    do {                                                                             \
        _Pragma("unroll")                                                            \
        for (int u = 0; u < NS; u++) {                                               \
            rgAh[u] = *reinterpret_cast<const uint4*>(pAh + u * 8);                  \
            rgAl[u] = *reinterpret_cast<const uint4*>(pAl + u * 8);                  \
            rgBh[u] = *reinterpret_cast<const uint4*>(pBh + u * 8);                  \
            rgBl[u] = *reinterpret_cast<const uint4*>(pBl + u * 8);                  \
        }                                                                            \
    } while (0)

#define STAGE_STORE(BASE)                                                            \
    do {                                                                             \
        char* base_ = (BASE);                                                        \
        _Pragma("unroll")                                                            \
        for (int u = 0; u < NS; u++) {                                               \
            *reinterpret_cast<uint4*>(base_ + sts_off + u * 16)            = rgAh[u];\
            *reinterpret_cast<uint4*>(base_ + ARRB + sts_off + u * 16)     = rgAl[u];\
            *reinterpret_cast<uint4*>(base_ + 2*ARRB + sts_off + u * 16)   = rgBh[u];\
            *reinterpret_cast<uint4*>(base_ + 3*ARRB + sts_off + u * 16)   = rgBl[u];\
        }                                                                            \
    } while (0)

#define ADV() do { pAh += KCH; pAl += KCH; pBh += KCH; pBl += KCH; } while (0)

template<int KCH>
__global__ __launch_bounds__(256, 1) void tgemm(
    const bf16* __restrict__ Ah, const bf16* __restrict__ Al, long lda, long saB,
    const bf16* __restrict__ Bh, const bf16* __restrict__ Bl, long ldb, long sbB,
    float* __restrict__ C, bf16* __restrict__ Ch, bf16* __restrict__ Cl,
    bf16* __restrict__ Th, bf16* __restrict__ Tl,   // FT outputs (mode 2 only)
    long ldc, long scB, int K, const float* __restrict__ bias,
    int mode, int bXor, int bShr)
{
    constexpr int NS    = KCH / 16;     // ks steps per chunk; also uint4/thread/array
    constexpr int ROWSB = KCH + 8;
    constexpr int ARRB  = 128 * ROWSB * 2;
    constexpr int STGB  = 4 * ARRB;

    extern __shared__ char smem[];
    const uint32_t s0 = smem_u32(smem);
    const int tid = threadIdx.x;
    const int lane = tid & 31;
    const int wid = tid >> 5;
    const int bz = blockIdx.z;
    Ah += (long)bz * saB; Al += (long)bz * saB;
    const long bOff = (long)((bz ^ bXor) >> bShr) * sbB;
    Bh += bOff; Bl += bOff;
    const long i0 = (long)blockIdx.y * 128;
    const long j0 = (long)blockIdx.x * 128;

    // staging: row = tid>>1, k-half = (tid&1)*(KCH/2)
    const int srow = tid >> 1;
    const int skh  = (tid & 1) * (KCH / 2);
    const bf16* pAh = Ah + (i0 + srow) * lda + skh;
    const bf16* pAl = Al + (i0 + srow) * lda + skh;
    const bf16* pBh = Bh + (j0 + srow) * ldb + skh;
    const bf16* pBl = Bl + (j0 + srow) * ldb + skh;
    const int sts_off = (srow * ROWSB + skh) * 2;

    const int m0 = (wid & 1) * 64;
    const int n0 = (wid >> 1) * 32;
    const int a_base = (m0 + (lane & 15)) * ROWSB + ((lane >> 4) << 3);
    const int b_base = (n0 + ((lane >> 4) << 3) + (lane & 7)) * ROWSB +
                       (((lane >> 3) & 1) << 3);

    float acc[4][4][4];
#pragma unroll
    for (int mt = 0; mt < 4; mt++)
#pragma unroll
        for (int nt = 0; nt < 4; nt++)
#pragma unroll
            for (int e = 0; e < 4; e++) acc[mt][nt][e] = 0.f;

    uint32_t f_ah[2][4][4], f_al[2][4][4], f_bh[2][4][2], f_bl[2][4][2];
    uint4 rgAh[NS], rgAl[NS], rgBh[NS], rgBl[NS];

    const int NC = K / KCH;

    // prologue
    STAGE_LOAD();
    STAGE_STORE(smem);
    if (NC > 1) { ADV(); STAGE_LOAD(); }
    __syncthreads();
    LOAD_FRAGS(0, s0, 0);

    for (int c = 0; c < NC; c++) {
        const uint32_t sb = s0 + (uint32_t)(c & 1) * STGB;
#pragma unroll
        for (int ks = 0; ks < NS; ks++) {
            if (ks + 1 < NS) LOAD_FRAGS((ks + 1) & 1, sb, (ks + 1) * 16);
            DO_MMA(ks & 1);
            if (ks == 0 && c + 1 < NC) {
                STAGE_STORE(smem + ((c + 1) & 1) * STGB);
                if (NS == 2 && c + 2 < NC) { ADV(); STAGE_LOAD(); }
            }
            if (NS > 2 && ks == 1 && c + 2 < NC) { ADV(); STAGE_LOAD(); }
        }
        __syncthreads();
        if (c + 1 < NC)
            LOAD_FRAGS(0, s0 + (uint32_t)((c + 1) & 1) * STGB, 0);
    }

    const int er = lane >> 2;
    const int ec = (lane & 3) << 1;

    if (mode == 2) {
        // conv1 pooled epilogue: tile = 128 ch x 128 pix (2 image rows of 64)
        float* spool = reinterpret_cast<float*>(smem);   // 128 x 132
#pragma unroll
        for (int mt = 0; mt < 4; mt++) {
            int r0 = m0 + mt * 16 + er;
#pragma unroll
            for (int nt = 0; nt < 4; nt++) {
                int jc = n0 + nt * 8 + ec;
                *reinterpret_cast<float2*>(&spool[(r0)     * 132 + jc]) =
                    make_float2(acc[mt][nt][0], acc[mt][nt][1]);
                *reinterpret_cast<float2*>(&spool[(r0 + 8) * 132 + jc]) =
                    make_float2(acc[mt][nt][2], acc[mt][nt][3]);
            }
        }
        __syncthreads();
        const int cl = tid >> 1;           // channel row 0..127
        const int half = tid & 1;          // ow half
        const float bv = bias[i0 + cl];
        uint32_t hw[8], lw[8];
#pragma unroll
        for (int o = 0; o < 16; o += 2) {
            float vv[2];
#pragma unroll
            for (int u = 0; u < 2; u++) {
                int owg = half * 16 + o + u;
                float2 a0 = *reinterpret_cast<float2*>(&spool[cl * 132 + 2 * owg]);
                float2 a1 = *reinterpret_cast<float2*>(&spool[cl * 132 + 64 + 2 * owg]);
                vv[u] = fmaxf(fmaxf(a0.x, a0.y), fmaxf(a1.x, a1.y)) + bv;
            }
            uint32_t hp = packbf(vv[0], vv[1]);
            hw[o >> 1] = hp;
            lw[o >> 1] = packbf(vv[0] - bflo(hp), vv[1] - bfhi(hp));
        }
        long q0 = (long)(j0 >> 2) + half * 16;
        long off = (long)bz * scB + (i0 + cl) * ldc + q0;
        *reinterpret_cast<uint4*>(Ch + off)     = *reinterpret_cast<uint4*>(hw);
        *reinterpret_cast<uint4*>(Ch + off + 8) = *reinterpret_cast<uint4*>(hw + 4);
        *reinterpret_cast<uint4*>(Cl + off)     = *reinterpret_cast<uint4*>(lw);
        *reinterpret_cast<uint4*>(Cl + off + 8) = *reinterpret_cast<uint4*>(lw + 4);

        // ---- fused FT = F^T for this 32q x 128c block ----
        __syncthreads();   // all spool (float) reads done
        uint16_t* sth = reinterpret_cast<uint16_t*>(smem);           // 32q x 128c bf16
        uint16_t* stl = reinterpret_cast<uint16_t*>(smem + 8192);
#pragma unroll
        for (int o = 0; o < 8; o++) {
            int q = half * 16 + 2 * o;
            sth[(q)     * 128 + cl] = (uint16_t)(hw[o] & 0xFFFF);
            sth[(q + 1) * 128 + cl] = (uint16_t)(hw[o] >> 16);
            stl[(q)     * 128 + cl] = (uint16_t)(lw[o] & 0xFFFF);
            stl[(q + 1) * 128 + cl] = (uint16_t)(lw[o] >> 16);
        }
        __syncthreads();
        {
            int q  = tid >> 3;             // 0..31
            int ch = (tid & 7) * 16;       // 16 bf16 = 2 uint4
            long fo = (long)bz * scB + ((long)(j0 >> 2) + q) * C_MID + i0 + ch;
            const uint4* srcH = reinterpret_cast<const uint4*>(sth + q * 128 + ch);
            const uint4* srcL = reinterpret_cast<const uint4*>(stl + q * 128 + ch);
            *reinterpret_cast<uint4*>(Th + fo)     = srcH[0];
            *reinterpret_cast<uint4*>(Th + fo + 8) = srcH[1];
            *reinterpret_cast<uint4*>(Tl + fo)     = srcL[0];
            *reinterpret_cast<uint4*>(Tl + fo + 8) = srcL[1];
        }
        return;
    }

#pragma unroll
    for (int mt = 0; mt < 4; mt++) {
        long r0 = i0 + m0 + mt * 16 + er;
        long r1 = r0 + 8;
        float bv0 = bias ? bias[r0] : 0.f;
        float bv1 = bias ? bias[r1] : 0.f;
#pragma unroll
        for (int nt = 0; nt < 4; nt++) {
            long jc = j0 + n0 + nt * 8 + ec;
            float o00 = acc[mt][nt][0] + bv0, o01 = acc[mt][nt][1] + bv0;
            float o10 = acc[mt][nt][2] + bv1, o11 = acc[mt][nt][3] + bv1;
            if (mode == 0) {
                float* cb = C + (long)bz * scB;
                *reinterpret_cast<float2*>(cb + r0 * ldc + jc) = make_float2(o00, o01);
                *reinterpret_cast<float2*>(cb + r1 * ldc + jc) = make_float2(o10, o11);
            } else {
                bf16* chb = Ch + (long)bz * scB;
                bf16* clb = Cl + (long)bz * scB;
                uint32_t h0 = packbf(o00, o01);
                uint32_t h1 = packbf(o10, o11);
                *reinterpret_cast<uint32_t*>(chb + r0 * ldc + jc) = h0;
                *reinterpret_cast<uint32_t*>(chb + r1 * ldc + jc) = h1;
                *reinterpret_cast<uint32_t*>(clb + r0 * ldc + jc) =
                    packbf(o00 - bflo(h0), o01 - bfhi(h0));
                *reinterpret_cast<uint32_t*>(clb + r1 * ldc + jc) =
                    packbf(o10 - bflo(h1), o11 - bfhi(h1));
            }
        }
    }
}

// ================= conversion / movement kernels =================
__global__ void trans_split_kernel(const float* __restrict__ in,
                                   bf16* __restrict__ oh, bf16* __restrict__ ol,
                                   int R, int Cc)
{
    __shared__ float t[32][33];
    int bx = blockIdx.x * 32, by = blockIdx.y * 32;
    long base = (long)blockIdx.z * (long)R * Cc;
    int x = threadIdx.x, y = threadIdx.y;  // 32 x 8
#pragma unroll
    for (int i = 0; i < 32; i += 8)
        t[y + i][x] = in[base + (long)(by + y + i) * Cc + bx + x];
    __syncthreads();
#pragma unroll
    for (int i = 0; i < 32; i += 8) {
        float v = t[x][y + i];
        bf16 h = __float2bfloat16(v);
        long o = base + (long)(bx + y + i) * R + by + x;
        oh[o] = h;
        ol[o] = __float2bfloat16(v - __bfloat162float(h));
    }
}

__global__ void split_kernel(const float* __restrict__ in,
                             bf16* __restrict__ oh, bf16* __restrict__ ol, int n)
{
    int i = blockIdx.x * 256 + threadIdx.x;
    if (i >= n) return;
    float v = in[i];
    bf16 h = __float2bfloat16(v);
    oh[i] = h;
    ol[i] = __float2bfloat16(v - __bfloat162float(h));
}

__global__ void normsplit_kernel(const float* __restrict__ T,
                                 bf16* __restrict__ oh, bf16* __restrict__ ol)
{
    __shared__ float part[4][64];
    __shared__ float sinv[64];
    int pp = threadIdx.x & 63, qs = threadIdx.x >> 6;
    int p = blockIdx.x * 64 + pp;
    long base = (long)blockIdx.y * PHW * PHW;
    float ss = 0.f;
#pragma unroll 4
    for (int q = qs * 256; q < qs * 256 + 256; q++) {
        float x = fmaxf(T[base + (long)q * PHW + p], 0.f);
        ss += x * x;
    }
    part[qs][pp] = ss;
    __syncthreads();
    if (threadIdx.x < 64) {
        float s = part[0][threadIdx.x] + part[1][threadIdx.x] +
                  part[2][threadIdx.x] + part[3][threadIdx.x];
        sinv[threadIdx.x] = rsqrtf(s + 1e-6f);
    }
    __syncthreads();
    float inv = sinv[pp];
#pragma unroll 4
    for (int q = qs * 256; q < qs * 256 + 256; q++) {
        long idx = base + (long)q * PHW + p;
        float v = fmaxf(T[idx], 0.f) * inv;
        bf16 h = __float2bfloat16(v);
        oh[idx] = h;
        ol[idx] = __float2bfloat16(v - __bfloat162float(h));
    }
}

__global__ void upsample_kernel(const float* __restrict__ V, float* __restrict__ O)
{
    long i = (long)blockIdx.x * blockDim.x + threadIdx.x;
    int x = (int)(i & 63);
    int y = (int)((i >> 6) & 63);
    long co = i >> 12;
    const float s = 31.0f / 63.0f;
    float ys = y * s, xs = x * s;
    int y0 = (int)floorf(ys), x0 = (int)floorf(xs);
    float ty = ys - (float)y0, txx = xs - (float)x0;
    int y1 = min(y0 + 1, 31), x1 = min(x0 + 1, 31);
    const float* v = V + co * 1024;
    float v00 = v[y0 * 32 + x0], v01 = v[y0 * 32 + x1];
    float v10 = v[y1 * 32 + x0], v11 = v[y1 * 32 + x1];
    O[i] = (1.f - ty) * ((1.f - txx) * v00 + txx * v01) +
           ty * ((1.f - txx) * v10 + txx * v11);
}

// ================= launch =================
extern "C" void kernel_launch(void* const* d_in, const int* in_sizes, int n_in,
                              void* d_out, int out_size)
{
    const float* xa      = (const float*)d_in[0];
    const float* xb      = (const float*)d_in[1];
    const float* conv_w  = (const float*)d_in[2];
    const float* conv_b  = (const float*)d_in[3];
    const float* We      = (const float*)d_in[4];
    const float* We2     = (const float*)d_in[5];
    const float* conv2_w = (const float*)d_in[6];
    const float* conv2_b = (const float*)d_in[7];
    float* out = (float*)d_out;

    bf16 *XTh, *XTl, *Wh, *Wl, *Fh, *Fl, *FTh, *FTl, *WTh, *WTl;
    bf16 *GTh, *GTl, *MTh, *MTl, *ETh, *ETl, *C2h, *C2l;
    float *MT, *V;
    cudaGetSymbolAddress((void**)&XTh, g_XTh);  cudaGetSymbolAddress((void**)&XTl, g_XTl);
    cudaGetSymbolAddress((void**)&Wh,  g_Wh);   cudaGetSymbolAddress((void**)&Wl,  g_Wl);
    cudaGetSymbolAddress((void**)&Fh,  g_Fh);   cudaGetSymbolAddress((void**)&Fl,  g_Fl);
    cudaGetSymbolAddress((void**)&FTh, g_FTh);  cudaGetSymbolAddress((void**)&FTl, g_FTl);
    cudaGetSymbolAddress((void**)&WTh, g_WTh);  cudaGetSymbolAddress((void**)&WTl, g_WTl);
    cudaGetSymbolAddress((void**)&GTh, g_GTh);  cudaGetSymbolAddress((void**)&GTl, g_GTl);
    cudaGetSymbolAddress((void**)&MT,  g_MT);
    cudaGetSymbolAddress((void**)&MTh, g_MTh);  cudaGetSymbolAddress((void**)&MTl, g_MTl);
    cudaGetSymbolAddress((void**)&ETh, g_ETh);  cudaGetSymbolAddress((void**)&ETl, g_ETl);
    cudaGetSymbolAddress((void**)&C2h, g_C2h);  cudaGetSymbolAddress((void**)&C2l, g_C2l);
    cudaGetSymbolAddress((void**)&V,   g_V);

    const int SM32 = 2 * 4 * 128 * 40 * 2;   // 81920
    const int SM64 = 2 * 4 * 128 * 72 * 2;   // 147456
    cudaFuncSetAttribute(tgemm<32>, cudaFuncAttributeMaxDynamicSharedMemorySize, SM32);
    cudaFuncSetAttribute(tgemm<64>, cudaFuncAttributeMaxDynamicSharedMemorySize, SM64);

    const long MM = (long)PHW * C_MID;   // 1M elems per batch
    dim3 tp(32, 8);

    // weights -> split bf16
    split_kernel<<<(C_MID * C_IN + 255) / 256, 256>>>(conv_w, Wh, Wl, C_MID * C_IN);
    split_kernel<<<(256 * C_MID + 255) / 256, 256>>>(conv2_w, C2h, C2l, 256 * C_MID);
    // We/We2 -> transposed split (WT[0], WT[1])
    trans_split_kernel<<<dim3(32, 32, 1), tp>>>(We,  WTh, WTl, C_MID, C_MID);
    trans_split_kernel<<<dim3(32, 32, 1), tp>>>(We2, WTh + (size_t)C_MID * C_MID,
                                                WTl + (size_t)C_MID * C_MID, C_MID, C_MID);
    // xa -> XT[0..7], xb -> XT[8..15]
    trans_split_kernel<<<dim3(128, 8, BATCH), tp>>>(xa, XTh, XTl, C_IN, HW);
    trans_split_kernel<<<dim3(128, 8, BATCH), tp>>>(
        xb, XTh + (size_t)BATCH * HW * C_IN, XTl + (size_t)BATCH * HW * C_IN, C_IN, HW);

    // conv1 + fused pool + fused F-transpose -> F[c][q] and FT[q][c], all 16 batches
    tgemm<32><<<dim3(HW / 128, C_MID / 128, NB), 256, SM32>>>(
        Wh, Wl, C_IN, 0,
        XTh, XTl, C_IN, (long)HW * C_IN,
        nullptr, Fh, Fl, FTh, FTl, PHW, MM, C_IN, conv_b, 2, 0, 0);

    // GT[q,c] = sum_d FT[q,d] * WT[path][c,d]   (path = bz>>3)
    tgemm<64><<<dim3(C_MID / 128, PHW / 128, NB), 256, SM64>>>(
        FTh, FTl, C_MID, MM,
        WTh, WTl, C_MID, (long)C_MID * C_MID,
        nullptr, GTh, GTl, nullptr, nullptr, C_MID, MM, C_MID, nullptr, 1, 0, 3);

    // fmT[q,p] = sum_c GT[q,c] * FT_other[p,c]   (other image = bz^8)
    tgemm<64><<<dim3(PHW / 128, PHW / 128, NB), 256, SM64>>>(
        GTh, GTl, C_MID, MM,
        FTh, FTl, C_MID, MM,
        MT, nullptr, nullptr, nullptr, nullptr, PHW, MM, C_MID, nullptr, 0, 8, 0);

    // relu + L2 norm over q per column p, write split
    normsplit_kernel<<<dim3(PHW / 64, NB), 256>>>(MT, MTh, MTl);

    // ET[k,q] = sum_p F[k,p] * Mn[q,p]
    tgemm<64><<<dim3(PHW / 128, C_MID / 128, NB), 256, SM64>>>(
        Fh, Fl, PHW, MM,
        MTh, MTl, PHW, MM,
        nullptr, ETh, ETl, nullptr, nullptr, PHW, MM, PHW, nullptr, 1, 0, 0);

    // V[o,k] = sum_q c2w[o,q] * ET[k,q] + b
    tgemm<64><<<dim3(PHW / 128, 256 / 128, NB), 256, SM64>>>(
        C2h, C2l, C_MID, 0,
        ETh, ETl, C_MID, MM,
        V, nullptr, nullptr, nullptr, nullptr, PHW, (long)256 * PHW, C_MID, conv2_b, 0, 0, 0);

    // upsample 2x align_corners, all 16 batches straight into out
    upsample_kernel<<<(NB * 256 * HW) / 256, 256>>>(V, out);
}

// round 17
// speedup vs baseline: 1.5587x; 1.0057x over previous
#include <cuda_runtime.h>
#include <cuda_bf16.h>
#include <cstdint>

#define BATCH 8
#define NB    16     // both images / both paths merged
#define C_IN  256
#define C_MID 1024
#define HW    4096   // 64*64
#define PHW   1024   // 32*32
typedef __nv_bfloat16 bf16;

// ---------------- scratch (static device globals; no allocation) ----------------
__device__ bf16 g_XTh[(size_t)NB * HW * C_IN];
__device__ bf16 g_XTl[(size_t)NB * HW * C_IN];
__device__ bf16 g_Wh [(size_t)C_MID * C_IN];
__device__ bf16 g_Wl [(size_t)C_MID * C_IN];
__device__ bf16 g_Fh [(size_t)NB * C_MID * PHW];   // [0..7]=Fa, [8..15]=Fb
__device__ bf16 g_Fl [(size_t)NB * C_MID * PHW];
__device__ bf16 g_FTh[(size_t)NB * PHW * C_MID];
__device__ bf16 g_FTl[(size_t)NB * PHW * C_MID];
__device__ bf16 g_WTh[(size_t)2 * C_MID * C_MID];  // [0]=WeT, [1]=We2T
__device__ bf16 g_WTl[(size_t)2 * C_MID * C_MID];
__device__ bf16 g_GTh[(size_t)NB * PHW * C_MID];
__device__ bf16 g_GTl[(size_t)NB * PHW * C_MID];
__device__ float g_MT[(size_t)NB * PHW * PHW];
__device__ bf16 g_MTh[(size_t)NB * PHW * PHW];
__device__ bf16 g_MTl[(size_t)NB * PHW * PHW];
__device__ bf16 g_ETh[(size_t)NB * C_MID * PHW];
__device__ bf16 g_ETl[(size_t)NB * C_MID * PHW];
__device__ bf16 g_C2h[(size_t)256 * C_MID];
__device__ bf16 g_C2l[(size_t)256 * C_MID];
__device__ float g_V [(size_t)NB * 256 * PHW];

// ================= helpers =================
__device__ __forceinline__ uint32_t smem_u32(const void* p) {
    uint32_t a;
    asm("{ .reg .u64 t; cvta.to.shared.u64 t, %1; cvt.u32.u64 %0, t; }" : "=r"(a) : "l"(p));
    return a;
}
__device__ __forceinline__ void ldsm4(uint32_t* r, uint32_t addr) {
    asm volatile("ldmatrix.sync.aligned.m8n8.x4.shared.b16 {%0,%1,%2,%3}, [%4];"
                 : "=r"(r[0]), "=r"(r[1]), "=r"(r[2]), "=r"(r[3]) : "r"(addr));
}
__device__ __forceinline__ void mma16816(float* d, const uint32_t* a, const uint32_t* b) {
    asm volatile(
        "mma.sync.aligned.m16n8k16.row.col.f32.bf16.bf16.f32 "
        "{%0,%1,%2,%3}, {%4,%5,%6,%7}, {%8,%9}, {%0,%1,%2,%3};"
        : "+f"(d[0]), "+f"(d[1]), "+f"(d[2]), "+f"(d[3])
        : "r"(a[0]), "r"(a[1]), "r"(a[2]), "r"(a[3]), "r"(b[0]), "r"(b[1]));
}
__device__ __forceinline__ uint32_t packbf(float x, float y) {
    uint32_t r;
    asm("cvt.rn.bf16x2.f32 %0, %1, %2;" : "=r"(r) : "f"(y), "f"(x));
    return r;
}
__device__ __forceinline__ float bflo(uint32_t p) { return __uint_as_float(p << 16); }
__device__ __forceinline__ float bfhi(uint32_t p) { return __uint_as_float(p & 0xFFFF0000u); }

// ================= tensor GEMM: 128x128 tile, templated K-chunk =================
// C[i,j](+bias[i]) = sum_k (Ah+Al)[i,k] * (Bh+Bl)[j,k]  (3-term split)
// A batch: bz.  B batch: (bz ^ bXor) >> bShr.
// mode 0: fp32 C.  mode 1: split bf16 Ch/Cl.
// mode 2: conv1 pooled epilogue -> F[c][q] AND FT[q][c] (fused).

#define LOAD_FRAGS(P, SB, KO)                                                        \
    do {                                                                             \
        _Pragma("unroll")                                                            \
        for (int mt = 0; mt < 4; mt++)                                               \
            ldsm4(f_ah[P][mt], (SB) + (uint32_t)(a_base + mt * 16 * ROWSB + (KO)) * 2); \
        _Pragma("unroll")                                                            \
        for (int mt = 0; mt < 4; mt++)                                               \
            ldsm4(f_al[P][mt], (SB) + ARRB + (uint32_t)(a_base + mt * 16 * ROWSB + (KO)) * 2); \
        _Pragma("unroll")                                                            \
        for (int nt2 = 0; nt2 < 2; nt2++) {                                          \
            uint32_t t[4];                                                           \
            ldsm4(t, (SB) + 2*ARRB + (uint32_t)(b_base + nt2 * 16 * ROWSB + (KO)) * 2); \
            f_bh[P][nt2*2][0] = t[0]; f_bh[P][nt2*2][1] = t[1];                      \
            f_bh[P][nt2*2+1][0] = t[2]; f_bh[P][nt2*2+1][1] = t[3];                  \
        }                                                                            \
        _Pragma("unroll")                                                            \
        for (int nt2 = 0; nt2 < 2; nt2++) {                                          \
            uint32_t t[4];                                                           \
            ldsm4(t, (SB) + 3*ARRB + (uint32_t)(b_base + nt2 * 16 * ROWSB + (KO)) * 2); \
            f_bl[P][nt2*2][0] = t[0]; f_bl[P][nt2*2][1] = t[1];                      \
            f_bl[P][nt2*2+1][0] = t[2]; f_bl[P][nt2*2+1][1] = t[3];                  \
        }                                                                            \
    } while (0)

#define DO_MMA(P)                                                                    \
    do {                                                                             \
        _Pragma("unroll")                                                            \
        for (int mt = 0; mt < 4; mt++)                                               \
            _Pragma("unroll")                                                        \
            for (int nt = 0; nt < 4; nt++)                                           \
                mma16816(acc[mt][nt], f_ah[P][mt], f_bh[P][nt]);                     \
        _Pragma("unroll")                                                            \
        for (int mt = 0; mt < 4; mt++)                                               \
            _Pragma("unroll")                                                        \
            for (int nt = 0; nt < 4; nt++)                                           \
                mma16816(acc[mt][nt], f_ah[P][mt], f_bl[P][nt]);                     \
        _Pragma("unroll")                                                            \
        for (int mt = 0; mt < 4; mt++)                                               \
            _Pragma("unroll")                                                        \
            for (int nt = 0; nt < 4; nt++)                                           \
                mma16816(acc[mt][nt], f_al[P][mt], f_bh[P][nt]);                     \
    } while (0)

#define STAGE_LOAD()                                                                 \
    do {                                                                             \
        _Pragma("unroll")                                                            \
        for (int u = 0; u < NS; u++) {                                               \
            rgAh[u] = *reinterpret_cast<const uint4*>(pAh + u * 8);                  \
            rgAl[u] = *reinterpret_cast<const uint4*>(pAl + u * 8);                  \
            rgBh[u] = *reinterpret_cast<const uint4*>(pBh + u * 8);                  \
            rgBl[u] = *reinterpret_cast<const uint4*>(pBl + u * 8);                  \
        }                                                                            \
    } while (0)

#define STAGE_STORE(BASE)                                                            \
    do {                                                                             \
        char* base_ = (BASE);                                                        \
        _Pragma("unroll")                                                            \
        for (int u = 0; u < NS; u++) {                                               \
            *reinterpret_cast<uint4*>(base_ + sts_off + u * 16)            = rgAh[u];\
            *reinterpret_cast<uint4*>(base_ + ARRB + sts_off + u * 16)     = rgAl[u];\
            *reinterpret_cast<uint4*>(base_ + 2*ARRB + sts_off + u * 16)   = rgBh[u];\
            *reinterpret_cast<uint4*>(base_ + 3*ARRB + sts_off + u * 16)   = rgBl[u];\
        }                                                                            \
    } while (0)

#define ADV() do { pAh += KCH; pAl += KCH; pBh += KCH; pBl += KCH; } while (0)

template<int KCH>
__global__ __launch_bounds__(256, 1) void tgemm(
    const bf16* __restrict__ Ah, const bf16* __restrict__ Al, long lda, long saB,
    const bf16* __restrict__ Bh, const bf16* __restrict__ Bl, long ldb, long sbB,
    float* __restrict__ C, bf16* __restrict__ Ch, bf16* __restrict__ Cl,
    bf16* __restrict__ Th, bf16* __restrict__ Tl,   // FT outputs (mode 2 only)
    long ldc, long scB, int K, const float* __restrict__ bias,
    int mode, int bXor, int bShr)
{
    constexpr int NS    = KCH / 16;     // ks steps per chunk; also uint4/thread/array
    constexpr int ROWSB = KCH + 8;
    constexpr int ARRB  = 128 * ROWSB * 2;
    constexpr int STGB  = 4 * ARRB;

    extern __shared__ char smem[];
    const uint32_t s0 = smem_u32(smem);
    const int tid = threadIdx.x;
    const int lane = tid & 31;
    const int wid = tid >> 5;
    const int bz = blockIdx.z;
    Ah += (long)bz * saB; Al += (long)bz * saB;
    const long bOff = (long)((bz ^ bXor) >> bShr) * sbB;
    Bh += bOff; Bl += bOff;
    const long i0 = (long)blockIdx.y * 128;
    const long j0 = (long)blockIdx.x * 128;

    // staging: row = tid>>1, k-half = (tid&1)*(KCH/2)
    const int srow = tid >> 1;
    const int skh  = (tid & 1) * (KCH / 2);
    const bf16* pAh = Ah + (i0 + srow) * lda + skh;
    const bf16* pAl = Al + (i0 + srow) * lda + skh;
    const bf16* pBh = Bh + (j0 + srow) * ldb + skh;
    const bf16* pBl = Bl + (j0 + srow) * ldb + skh;
    const int sts_off = (srow * ROWSB + skh) * 2;

    const int m0 = (wid & 1) * 64;
    const int n0 = (wid >> 1) * 32;
    const int a_base = (m0 + (lane & 15)) * ROWSB + ((lane >> 4) << 3);
    const int b_base = (n0 + ((lane >> 4) << 3) + (lane & 7)) * ROWSB +
                       (((lane >> 3) & 1) << 3);

    float acc[4][4][4];
#pragma unroll
    for (int mt = 0; mt < 4; mt++)
#pragma unroll
        for (int nt = 0; nt < 4; nt++)
#pragma unroll
            for (int e = 0; e < 4; e++) acc[mt][nt][e] = 0.f;

    uint32_t f_ah[2][4][4], f_al[2][4][4], f_bh[2][4][2], f_bl[2][4][2];
    uint4 rgAh[NS], rgAl[NS], rgBh[NS], rgBl[NS];

    const int NC = K / KCH;

    // prologue
    STAGE_LOAD();
    STAGE_STORE(smem);
    if (NC > 1) { ADV(); STAGE_LOAD(); }
    __syncthreads();
    LOAD_FRAGS(0, s0, 0);

    for (int c = 0; c < NC; c++) {
        const uint32_t sb = s0 + (uint32_t)(c & 1) * STGB;
#pragma unroll
        for (int ks = 0; ks < NS; ks++) {
            if (ks + 1 < NS) LOAD_FRAGS((ks + 1) & 1, sb, (ks + 1) * 16);
            DO_MMA(ks & 1);
            if (ks == 0 && c + 1 < NC) {
                STAGE_STORE(smem + ((c + 1) & 1) * STGB);
                if (NS == 2 && c + 2 < NC) { ADV(); STAGE_LOAD(); }
            }
            if (NS > 2 && ks == 1 && c + 2 < NC) { ADV(); STAGE_LOAD(); }
        }
        __syncthreads();
        if (c + 1 < NC)
            LOAD_FRAGS(0, s0 + (uint32_t)((c + 1) & 1) * STGB, 0);
    }

    const int er = lane >> 2;
    const int ec = (lane & 3) << 1;

    if (mode == 2) {
        // conv1 pooled epilogue: tile = 128 ch x 128 pix (2 image rows of 64)
        float* spool = reinterpret_cast<float*>(smem);   // 128 x 132
#pragma unroll
        for (int mt = 0; mt < 4; mt++) {
            int r0 = m0 + mt * 16 + er;
#pragma unroll
            for (int nt = 0; nt < 4; nt++) {
                int jc = n0 + nt * 8 + ec;
                *reinterpret_cast<float2*>(&spool[(r0)     * 132 + jc]) =
                    make_float2(acc[mt][nt][0], acc[mt][nt][1]);
                *reinterpret_cast<float2*>(&spool[(r0 + 8) * 132 + jc]) =
                    make_float2(acc[mt][nt][2], acc[mt][nt][3]);
            }
        }
        __syncthreads();
        const int cl = tid >> 1;           // channel row 0..127
        const int half = tid & 1;          // ow half
        const float bv = bias[i0 + cl];
        uint32_t hw[8], lw[8];
#pragma unroll
        for (int o = 0; o < 16; o += 2) {
            float vv[2];
#pragma unroll
            for (int u = 0; u < 2; u++) {
                int owg = half * 16 + o + u;
                float2 a0 = *reinterpret_cast<float2*>(&spool[cl * 132 + 2 * owg]);
                float2 a1 = *reinterpret_cast<float2*>(&spool[cl * 132 + 64 + 2 * owg]);
                vv[u] = fmaxf(fmaxf(a0.x, a0.y), fmaxf(a1.x, a1.y)) + bv;
            }
            uint32_t hp = packbf(vv[0], vv[1]);
            hw[o >> 1] = hp;
            lw[o >> 1] = packbf(vv[0] - bflo(hp), vv[1] - bfhi(hp));
        }
        long q0 = (long)(j0 >> 2) + half * 16;
        long off = (long)bz * scB + (i0 + cl) * ldc + q0;
        *reinterpret_cast<uint4*>(Ch + off)     = *reinterpret_cast<uint4*>(hw);
        *reinterpret_cast<uint4*>(Ch + off + 8) = *reinterpret_cast<uint4*>(hw + 4);
        *reinterpret_cast<uint4*>(Cl + off)     = *reinterpret_cast<uint4*>(lw);
        *reinterpret_cast<uint4*>(Cl + off + 8) = *reinterpret_cast<uint4*>(lw + 4);

        // ---- fused FT = F^T for this 32q x 128c block ----
        __syncthreads();   // all spool (float) reads done
        uint16_t* sth = reinterpret_cast<uint16_t*>(smem);           // 32q x 128c bf16
        uint16_t* stl = reinterpret_cast<uint16_t*>(smem + 8192);
#pragma unroll
        for (int o = 0; o < 8; o++) {
            int q = half * 16 + 2 * o;
            sth[(q)     * 128 + cl] = (uint16_t)(hw[o] & 0xFFFF);
            sth[(q + 1) * 128 + cl] = (uint16_t)(hw[o] >> 16);
            stl[(q)     * 128 + cl] = (uint16_t)(lw[o] & 0xFFFF);
            stl[(q + 1) * 128 + cl] = (uint16_t)(lw[o] >> 16);
        }
        __syncthreads();
        {
            int q  = tid >> 3;             // 0..31
            int ch = (tid & 7) * 16;       // 16 bf16 = 2 uint4
            long fo = (long)bz * scB + ((long)(j0 >> 2) + q) * C_MID + i0 + ch;
            const uint4* srcH = reinterpret_cast<const uint4*>(sth + q * 128 + ch);
            const uint4* srcL = reinterpret_cast<const uint4*>(stl + q * 128 + ch);
            *reinterpret_cast<uint4*>(Th + fo)     = srcH[0];
            *reinterpret_cast<uint4*>(Th + fo + 8) = srcH[1];
            *reinterpret_cast<uint4*>(Tl + fo)     = srcL[0];
            *reinterpret_cast<uint4*>(Tl + fo + 8) = srcL[1];
        }
        return;
    }

#pragma unroll
    for (int mt = 0; mt < 4; mt++) {
        long r0 = i0 + m0 + mt * 16 + er;
        long r1 = r0 + 8;
        float bv0 = bias ? bias[r0] : 0.f;
        float bv1 = bias ? bias[r1] : 0.f;
#pragma unroll
        for (int nt = 0; nt < 4; nt++) {
            long jc = j0 + n0 + nt * 8 + ec;
            float o00 = acc[mt][nt][0] + bv0, o01 = acc[mt][nt][1] + bv0;
            float o10 = acc[mt][nt][2] + bv1, o11 = acc[mt][nt][3] + bv1;
            if (mode == 0) {
                float* cb = C + (long)bz * scB;
                *reinterpret_cast<float2*>(cb + r0 * ldc + jc) = make_float2(o00, o01);
                *reinterpret_cast<float2*>(cb + r1 * ldc + jc) = make_float2(o10, o11);
            } else {
                bf16* chb = Ch + (long)bz * scB;
                bf16* clb = Cl + (long)bz * scB;
                uint32_t h0 = packbf(o00, o01);
                uint32_t h1 = packbf(o10, o11);
                *reinterpret_cast<uint32_t*>(chb + r0 * ldc + jc) = h0;
                *reinterpret_cast<uint32_t*>(chb + r1 * ldc + jc) = h1;
                *reinterpret_cast<uint32_t*>(clb + r0 * ldc + jc) =
                    packbf(o00 - bflo(h0), o01 - bfhi(h0));
                *reinterpret_cast<uint32_t*>(clb + r1 * ldc + jc) =
                    packbf(o10 - bflo(h1), o11 - bfhi(h1));
            }
        }
    }
}

// ================= conversion / movement kernels =================
__global__ void trans_split_kernel(const float* __restrict__ in,
                                   bf16* __restrict__ oh, bf16* __restrict__ ol,
                                   int R, int Cc)
{
    __shared__ float t[32][33];
    int bx = blockIdx.x * 32, by = blockIdx.y * 32;
    long base = (long)blockIdx.z * (long)R * Cc;
    int x = threadIdx.x, y = threadIdx.y;  // 32 x 8
#pragma unroll
    for (int i = 0; i < 32; i += 8)
        t[y + i][x] = in[base + (long)(by + y + i) * Cc + bx + x];
    __syncthreads();
#pragma unroll
    for (int i = 0; i < 32; i += 8) {
        float v = t[x][y + i];
        bf16 h = __float2bfloat16(v);
        long o = base + (long)(bx + y + i) * R + by + x;
        oh[o] = h;
        ol[o] = __float2bfloat16(v - __bfloat162float(h));
    }
}

// dual-source variant: bz<8 reads inA[bz], bz>=8 reads inB[bz-8]; output at [bz]
__global__ void trans_split2_kernel(const float* __restrict__ inA,
                                    const float* __restrict__ inB,
                                    bf16* __restrict__ oh, bf16* __restrict__ ol,
                                    int R, int Cc)
{
    __shared__ float t[32][33];
    int bx = blockIdx.x * 32, by = blockIdx.y * 32;
    int bz = blockIdx.z;
    const float* in = (bz < 8) ? (inA + (long)bz * R * Cc)
                               : (inB + (long)(bz - 8) * R * Cc);
    long obase = (long)bz * (long)R * Cc;
    int x = threadIdx.x, y = threadIdx.y;  // 32 x 8
#pragma unroll
    for (int i = 0; i < 32; i += 8)
        t[y + i][x] = in[(long)(by + y + i) * Cc + bx + x];
    __syncthreads();
#pragma unroll
    for (int i = 0; i < 32; i += 8) {
        float v = t[x][y + i];
        bf16 h = __float2bfloat16(v);
        long o = obase + (long)(bx + y + i) * R + by + x;
        oh[o] = h;
        ol[o] = __float2bfloat16(v - __bfloat162float(h));
    }
}

__global__ void split_kernel(const float* __restrict__ in,
                             bf16* __restrict__ oh, bf16* __restrict__ ol, int n)
{
    int i = blockIdx.x * 256 + threadIdx.x;
    if (i >= n) return;
    float v = in[i];
    bf16 h = __float2bfloat16(v);
    oh[i] = h;
    ol[i] = __float2bfloat16(v - __bfloat162float(h));
}

__global__ void normsplit_kernel(const float* __restrict__ T,
                                 bf16* __restrict__ oh, bf16* __restrict__ ol)
{
    __shared__ float part[4][64];
    __shared__ float sinv[64];
    int pp = threadIdx.x & 63, qs = threadIdx.x >> 6;
    int p = blockIdx.x * 64 + pp;
    long base = (long)blockIdx.y * PHW * PHW;
    float ss = 0.f;
#pragma unroll 4
    for (int q = qs * 256; q < qs * 256 + 256; q++) {
        float x = fmaxf(T[base + (long)q * PHW + p], 0.f);
        ss += x * x;
    }
    part[qs][pp] = ss;
    __syncthreads();
    if (threadIdx.x < 64) {
        float s = part[0][threadIdx.x] + part[1][threadIdx.x] +
                  part[2][threadIdx.x] + part[3][threadIdx.x];
        sinv[threadIdx.x] = rsqrtf(s + 1e-6f);
    }
    __syncthreads();
    float inv = sinv[pp];
#pragma unroll 4
    for (int q = qs * 256; q < qs * 256 + 256; q++) {
        long idx = base + (long)q * PHW + p;
        float v = fmaxf(T[idx], 0.f) * inv;
        bf16 h = __float2bfloat16(v);
        oh[idx] = h;
        ol[idx] = __float2bfloat16(v - __bfloat162float(h));
    }
}

__global__ void upsample_kernel(const float* __restrict__ V, float* __restrict__ O)
{
    long i = (long)blockIdx.x * blockDim.x + threadIdx.x;
    int x = (int)(i & 63);
    int y = (int)((i >> 6) & 63);
    long co = i >> 12;
    const float s = 31.0f / 63.0f;
    float ys = y * s, xs = x * s;
    int y0 = (int)floorf(ys), x0 = (int)floorf(xs);
    float ty = ys - (float)y0, txx = xs - (float)x0;
    int y1 = min(y0 + 1, 31), x1 = min(x0 + 1, 31);
    const float* v = V + co * 1024;
    float v00 = v[y0 * 32 + x0], v01 = v[y0 * 32 + x1];
    float v10 = v[y1 * 32 + x0], v11 = v[y1 * 32 + x1];
    O[i] = (1.f - ty) * ((1.f - txx) * v00 + txx * v01) +
           ty * ((1.f - txx) * v10 + txx * v11);
}

// ================= launch =================
extern "C" void kernel_launch(void* const* d_in, const int* in_sizes, int n_in,
                              void* d_out, int out_size)
{
    const float* xa      = (const float*)d_in[0];
    const float* xb      = (const float*)d_in[1];
    const float* conv_w  = (const float*)d_in[2];
    const float* conv_b  = (const float*)d_in[3];
    const float* We      = (const float*)d_in[4];
    const float* We2     = (const float*)d_in[5];
    const float* conv2_w = (const float*)d_in[6];
    const float* conv2_b = (const float*)d_in[7];
    float* out = (float*)d_out;

    bf16 *XTh, *XTl, *Wh, *Wl, *Fh, *Fl, *FTh, *FTl, *WTh, *WTl;
    bf16 *GTh, *GTl, *MTh, *MTl, *ETh, *ETl, *C2h, *C2l;
    float *MT, *V;
    cudaGetSymbolAddress((void**)&XTh, g_XTh);  cudaGetSymbolAddress((void**)&XTl, g_XTl);
    cudaGetSymbolAddress((void**)&Wh,  g_Wh);   cudaGetSymbolAddress((void**)&Wl,  g_Wl);
    cudaGetSymbolAddress((void**)&Fh,  g_Fh);   cudaGetSymbolAddress((void**)&Fl,  g_Fl);
    cudaGetSymbolAddress((void**)&FTh, g_FTh);  cudaGetSymbolAddress((void**)&FTl, g_FTl);
    cudaGetSymbolAddress((void**)&WTh, g_WTh);  cudaGetSymbolAddress((void**)&WTl, g_WTl);
    cudaGetSymbolAddress((void**)&GTh, g_GTh);  cudaGetSymbolAddress((void**)&GTl, g_GTl);
    cudaGetSymbolAddress((void**)&MT,  g_MT);
    cudaGetSymbolAddress((void**)&MTh, g_MTh);  cudaGetSymbolAddress((void**)&MTl, g_MTl);
    cudaGetSymbolAddress((void**)&ETh, g_ETh);  cudaGetSymbolAddress((void**)&ETl, g_ETl);
    cudaGetSymbolAddress((void**)&C2h, g_C2h);  cudaGetSymbolAddress((void**)&C2l, g_C2l);
    cudaGetSymbolAddress((void**)&V,   g_V);

    const int SM64 = 2 * 4 * 128 * 72 * 2;   // 147456
    cudaFuncSetAttribute(tgemm<64>, cudaFuncAttributeMaxDynamicSharedMemorySize, SM64);

    const long MM = (long)PHW * C_MID;   // 1M elems per batch
    dim3 tp(32, 8);

    // weights -> split bf16
    split_kernel<<<(C_MID * C_IN + 255) / 256, 256>>>(conv_w, Wh, Wl, C_MID * C_IN);
    split_kernel<<<(256 * C_MID + 255) / 256, 256>>>(conv2_w, C2h, C2l, 256 * C_MID);
    // We/We2 -> transposed split (WT[0], WT[1])
    trans_split_kernel<<<dim3(32, 32, 1), tp>>>(We,  WTh, WTl, C_MID, C_MID);
    trans_split_kernel<<<dim3(32, 32, 1), tp>>>(We2, WTh + (size_t)C_MID * C_MID,
                                                WTl + (size_t)C_MID * C_MID, C_MID, C_MID);
    // xa -> XT[0..7], xb -> XT[8..15] in one launch
    trans_split2_kernel<<<dim3(128, 8, NB), tp>>>(xa, xb, XTh, XTl, C_IN, HW);

    // conv1 + fused pool + fused F-transpose -> F[c][q] and FT[q][c], all 16 batches
    tgemm<64><<<dim3(HW / 128, C_MID / 128, NB), 256, SM64>>>(
        Wh, Wl, C_IN, 0,
        XTh, XTl, C_IN, (long)HW * C_IN,
        nullptr, Fh, Fl, FTh, FTl, PHW, MM, C_IN, conv_b, 2, 0, 0);

    // GT[q,c] = sum_d FT[q,d] * WT[path][c,d]   (path = bz>>3)
    tgemm<64><<<dim3(C_MID / 128, PHW / 128, NB), 256, SM64>>>(
        FTh, FTl, C_MID, MM,
        WTh, WTl, C_MID, (long)C_MID * C_MID,
        nullptr, GTh, GTl, nullptr, nullptr, C_MID, MM, C_MID, nullptr, 1, 0, 3);

    // fmT[q,p] = sum_c GT[q,c] * FT_other[p,c]   (other image = bz^8)
    tgemm<64><<<dim3(PHW / 128, PHW / 128, NB), 256, SM64>>>(
        GTh, GTl, C_MID, MM,
        FTh, FTl, C_MID, MM,
        MT, nullptr, nullptr, nullptr, nullptr, PHW, MM, C_MID, nullptr, 0, 8, 0);

    // relu + L2 norm over q per column p, write split
    normsplit_kernel<<<dim3(PHW / 64, NB), 256>>>(MT, MTh, MTl);

    // ET[k,q] = sum_p F[k,p] * Mn[q,p]
    tgemm<64><<<dim3(PHW / 128, C_MID / 128, NB), 256, SM64>>>(
        Fh, Fl, PHW, MM,
        MTh, MTl, PHW, MM,
        nullptr, ETh, ETl, nullptr, nullptr, PHW, MM, PHW, nullptr, 1, 0, 0);

    // V[o,k] = sum_q c2w[o,q] * ET[k,q] + b
    tgemm<64><<<dim3(PHW / 128, 256 / 128, NB), 256, SM64>>>(
        C2h, C2l, C_MID, 0,
        ETh, ETl, C_MID, MM,
        V, nullptr, nullptr, nullptr, nullptr, PHW, (long)256 * PHW, C_MID, conv2_b, 0, 0, 0);

    // upsample 2x align_corners, all 16 batches straight into out
    upsample_kernel<<<(NB * 256 * HW) / 256, 256>>>(V, out);
}